// round 1
// baseline (speedup 1.0000x reference)
#include <cuda_runtime.h>
#include <math.h>

#define Bq 8
#define Nn 512
#define NFEAT 32
#define NHID 128
#define NHEADS 4
#define MROWS (Bq*Nn)   // 4096

// ---------------- scratch (device globals; no allocation) ----------------
__device__ __align__(256) float g_bufA[MROWS*NHID];
__device__ __align__(256) float g_bufB[MROWS*NHID];
__device__ __align__(256) float g_tmp [MROWS*2*NHID];
__device__ __align__(256) float g_hp2 [MROWS*NHEADS*NHID];         // [b,n,H*o]
__device__ __align__(256) float g_Wh  [NHEADS*Bq*Nn*NHID];          // [z,n,o]
__device__ __align__(256) float g_att [NHEADS*Bq*Nn*Nn];            // [z,i,j]
__device__ __align__(256) float g_s1  [NHEADS*Bq*Nn];
__device__ __align__(256) float g_s2  [NHEADS*Bq*Nn];
__device__ __align__(256) float g_hf  [MROWS*NHID];
__device__ __align__(256) float g_ht  [MROWS*NHID];
__device__ __align__(256) unsigned g_mask [Bq*Nn*(Nn/32)];
__device__ __align__(256) unsigned g_maskT[Bq*Nn*(Nn/32)];

// ---------------- batched-offset descriptor ----------------
struct BOff { int mod; long inS; long outS; };
__device__ __forceinline__ long boff(BOff o, int z){
    return (long)(z % o.mod) * o.inS + (long)(z / o.mod) * o.outS;
}

// ---------------- generic batched GEMM: C = act(A @ W + bias) ----------------
// A: [M,K] ld=ldA  W: [K,N] ld=ldW  C: [M,N] ld=ldC.  Tile 64x64x16, 256 thr, 4x4 micro.
// All M%64==0, N%64==0, K%16==0 (true for every call here) -> no bounds checks.
template<int ACT>   // 0=none 1=lrelu(0.01) 2=elu
__global__ void __launch_bounds__(256) gemm_k(
    const float* __restrict__ A, BOff ao, int ldA,
    const float* __restrict__ W, BOff wo, int ldW,
    const float* __restrict__ bias, BOff bo,
    float* __restrict__ C, BOff co, int ldC,
    int K)
{
    int z = blockIdx.z;
    A += boff(ao, z); W += boff(wo, z); C += boff(co, z);
    if (bias) bias += boff(bo, z);

    __shared__ float As[16][68];   // transposed A tile [k][m], padded
    __shared__ float Bs[16][68];   // [k][n], padded (272B row stride, 16B aligned)

    int tid = threadIdx.x;
    int tx = tid & 15, ty = tid >> 4;
    int m0 = blockIdx.y * 64, n0 = blockIdx.x * 64;
    int arow = tid >> 2, acg = tid & 3;     // A loader: 64 rows x 4 col-groups
    int brow = tid >> 4, bcg = tid & 15;    // B loader: 16 rows x 16 col-groups

    float acc[4][4] = {};

    for (int k0 = 0; k0 < K; k0 += 16) {
        float4 av = *(const float4*)&A[(long)(m0 + arow) * ldA + k0 + acg * 4];
        float4 bv = *(const float4*)&W[(long)(k0 + brow) * ldW + n0 + bcg * 4];
        As[acg*4+0][arow] = av.x; As[acg*4+1][arow] = av.y;
        As[acg*4+2][arow] = av.z; As[acg*4+3][arow] = av.w;
        *(float4*)&Bs[brow][bcg*4] = bv;
        __syncthreads();
        #pragma unroll
        for (int kk = 0; kk < 16; kk++) {
            float4 af = *(const float4*)&As[kk][ty*4];
            float4 bf = *(const float4*)&Bs[kk][tx*4];
            float a_[4] = {af.x, af.y, af.z, af.w};
            float b_[4] = {bf.x, bf.y, bf.z, bf.w};
            #pragma unroll
            for (int i = 0; i < 4; i++)
                #pragma unroll
                for (int j = 0; j < 4; j++)
                    acc[i][j] = fmaf(a_[i], b_[j], acc[i][j]);
        }
        __syncthreads();
    }

    #pragma unroll
    for (int i = 0; i < 4; i++) {
        int m = m0 + ty * 4 + i;
        #pragma unroll
        for (int j = 0; j < 4; j++) {
            int n = n0 + tx * 4 + j;
            float v = acc[i][j];
            if (bias) v += bias[n];
            if (ACT == 1) v = v > 0.f ? v : 0.01f * v;
            else if (ACT == 2) v = v > 0.f ? v : (expf(v) - 1.f);
            C[(long)m * ldC + n] = v;
        }
    }
}

// ---------------- adjacency -> packed bitmask (normal + transposed) ----------------
__global__ void maskbuild_k(const int* __restrict__ adj,
                            unsigned* __restrict__ mb, unsigned* __restrict__ mbT)
{
    int i = blockIdx.x, b = blockIdx.y, j = threadIdx.x;  // block 512
    int lane = j & 31, w = j >> 5;
    unsigned bit  = adj[((long)b * Nn + i) * Nn + j] > 0;
    unsigned word = __ballot_sync(~0u, bit);
    if (!lane) mb[((long)b * Nn + i) * 16 + w] = word;
    unsigned bitT  = adj[((long)b * Nn + j) * Nn + i] > 0;
    unsigned wordT = __ballot_sync(~0u, bitT);
    if (!lane) mbT[((long)b * Nn + i) * 16 + w] = wordT;
}

// ---------------- s1/s2 = Wh . a[:o], Wh . a[o:] (one warp per row) ----------------
__global__ void s1s2_k(const float* __restrict__ Wh, const float* __restrict__ a_base,
                       float* __restrict__ s1, float* __restrict__ s2, int nrows)
{
    int warp = (blockIdx.x * blockDim.x + threadIdx.x) >> 5;
    int lane = threadIdx.x & 31;
    if (warp >= nrows) return;
    int z = warp / Nn;
    int h = z / Bq;                       // head index (0 for single-head case)
    const float* a = a_base + h * 256;
    const float* w = Wh + (long)warp * NHID;
    float4 wv = *(const float4*)&w[lane * 4];
    float4 a1 = *(const float4*)&a[lane * 4];
    float4 a2 = *(const float4*)&a[128 + lane * 4];
    float d1 = wv.x*a1.x + wv.y*a1.y + wv.z*a1.z + wv.w*a1.w;
    float d2 = wv.x*a2.x + wv.y*a2.y + wv.z*a2.z + wv.w*a2.w;
    for (int off = 16; off; off >>= 1) {
        d1 += __shfl_xor_sync(~0u, d1, off);
        d2 += __shfl_xor_sync(~0u, d2, off);
    }
    if (!lane) { s1[warp] = d1; s2[warp] = d2; }
}

// ---------------- masked softmax over rank-1 leaky scores ----------------
// att[z,i,j] = softmax_j( mask ? lrelu(s1[i]*s2[j]) : -inf ), zeroed where !mask
__global__ void softmax_k(const float* __restrict__ s1, const float* __restrict__ s2,
                          const unsigned* __restrict__ maskbits, float* __restrict__ att)
{
    int i = blockIdx.x, z = blockIdx.y, t = threadIdx.x;   // 128 threads
    int b = z % Bq;
    __shared__ float s2s[Nn];
    __shared__ unsigned mw[16];
    __shared__ float red[4];
    const float* s2z = s2 + (long)z * Nn;
    #pragma unroll
    for (int k = 0; k < 4; k++) s2s[t + k*128] = s2z[t + k*128];
    if (t < 16) mw[t] = maskbits[((long)b * Nn + i) * 16 + t];
    __syncthreads();

    float s1i = s1[(long)z * Nn + i];
    float e[4]; bool valid[4];
    float m = -1e30f;
    #pragma unroll
    for (int k = 0; k < 4; k++) {
        int j = t + k * 128;
        float v = s1i * s2s[j];
        v = v > 0.f ? v : 0.01f * v;
        bool ok = (mw[j >> 5] >> (j & 31)) & 1;
        e[k] = v; valid[k] = ok;
        if (ok && v > m) m = v;
    }
    for (int off = 16; off; off >>= 1) m = fmaxf(m, __shfl_xor_sync(~0u, m, off));
    if ((t & 31) == 0) red[t >> 5] = m;
    __syncthreads();
    m = fmaxf(fmaxf(red[0], red[1]), fmaxf(red[2], red[3]));

    float p[4]; float s = 0.f;
    #pragma unroll
    for (int k = 0; k < 4; k++) { p[k] = valid[k] ? expf(e[k] - m) : 0.f; s += p[k]; }
    for (int off = 16; off; off >>= 1) s += __shfl_xor_sync(~0u, s, off);
    __syncthreads();
    if ((t & 31) == 0) red[t >> 5] = s;
    __syncthreads();
    s = red[0] + red[1] + red[2] + red[3];
    float inv = s > 0.f ? 1.f / s : 0.f;

    float* arow = att + ((long)z * Nn + i) * Nn;
    #pragma unroll
    for (int k = 0; k < 4; k++) arow[t + k*128] = p[k] * inv;
}

// ---------------- out = layernorm(tA + tB), rows of 128 ----------------
__global__ void ln_res_k(const float* __restrict__ tA, const float* __restrict__ tB,
                         float* __restrict__ out)
{
    int row = blockIdx.x, t = threadIdx.x;   // 128 threads
    __shared__ float red[4];
    float x = tA[(long)row*128 + t] + tB[(long)row*128 + t];
    float s = x;
    for (int off = 16; off; off >>= 1) s += __shfl_xor_sync(~0u, s, off);
    if ((t & 31) == 0) red[t >> 5] = s;
    __syncthreads();
    float mean = (red[0]+red[1]+red[2]+red[3]) * (1.f/128.f);
    float d = x - mean;
    float v = d * d;
    __syncthreads();
    for (int off = 16; off; off >>= 1) v += __shfl_xor_sync(~0u, v, off);
    if ((t & 31) == 0) red[t >> 5] = v;
    __syncthreads();
    float var = (red[0]+red[1]+red[2]+red[3]) * (1.f/128.f);
    out[(long)row*128 + t] = d * rsqrtf(var + 1e-5f);
}

// ---------------- final: out[b] = mean_n concat(hf,ht) . proj_W + proj_b ----------------
__global__ void final_k(const float* __restrict__ hf, const float* __restrict__ ht,
                        const float* __restrict__ pW, const float* __restrict__ pb,
                        float* __restrict__ out)
{
    int b = blockIdx.x, t = threadIdx.x;    // 256 threads
    const float* src = (t < 128) ? hf : ht;
    int f = t & 127;
    float w = pW[t];
    float acc = 0.f;
    for (int n = 0; n < Nn; n++) acc += src[((long)b * Nn + n) * 128 + f];
    acc *= w;
    __shared__ float red[8];
    for (int off = 16; off; off >>= 1) acc += __shfl_xor_sync(~0u, acc, off);
    if ((t & 31) == 0) red[t >> 5] = acc;
    __syncthreads();
    if (t == 0) {
        float s = 0.f;
        #pragma unroll
        for (int k = 0; k < 8; k++) s += red[k];
        out[b] = s / (float)Nn + pb[0];
    }
}

// ---------------- host orchestration ----------------
static inline BOff Z()            { return BOff{1, 0, 0}; }
static inline BOff perZ(long s)   { return BOff{1, 0, s}; }

static void attn_block(const float* in, float* out, int blk,
                       const unsigned* mb,
                       const float* att_W, const float* att_a,
                       const float* resh_W, const float* resh_b,
                       float* Wh, float* att, float* hp2, float* tmp,
                       float* s1, float* s2)
{
    const float* Wblk = att_W  + (long)blk * NHEADS * 128 * 128;
    const float* ablk = att_a  + (long)blk * NHEADS * 256;
    const float* rW   = resh_W + (long)blk * 512 * 128;
    const float* rb   = resh_b + (long)blk * 128;
    const int Zc = NHEADS * Bq;   // 32

    // Wh[z] = in[b] @ W[h]     (z = h*B + b)
    gemm_k<0><<<dim3(2, 8, Zc), 256>>>(
        in,   BOff{Bq, (long)Nn*128, 0}, 128,
        Wblk, BOff{Bq, 0, 128*128},      128,
        nullptr, Z(),
        Wh, perZ((long)Nn*128), 128, 128);
    // s1/s2
    s1s2_k<<<(Zc*Nn)/8, 256>>>(Wh, ablk, s1, s2, Zc*Nn);
    // att
    softmax_k<<<dim3(Nn, Zc), 128>>>(s1, s2, mb, att);
    // hp2[b,n,h*128+o] = elu( att[z] @ Wh[z] )
    gemm_k<2><<<dim3(2, 8, Zc), 256>>>(
        att, perZ((long)Nn*Nn), Nn,
        Wh,  perZ((long)Nn*128), 128,
        nullptr, Z(),
        hp2, BOff{Bq, (long)Nn*512, 128}, 512, Nn);
    // tmp = hp2 @ resh_W + resh_b
    gemm_k<0><<<dim3(2, 64, 1), 256>>>(
        hp2, Z(), 512,
        rW,  Z(), 128,
        rb,  Z(),
        tmp, Z(), 128, 512);
    // out = LN(tmp + in)
    ln_res_k<<<MROWS, 128>>>(tmp, in, out);
}

static void out_gat(const float* in, float* dst, int widx,
                    const unsigned* mb,
                    const float* out_W, const float* out_a,
                    float* Wh, float* att, float* s1, float* s2)
{
    const float* Wblk = out_W + (long)widx * 128 * 128;
    const float* ablk = out_a + (long)widx * 256;
    const int Zc = Bq;   // single head -> 8 batches

    gemm_k<0><<<dim3(2, 8, Zc), 256>>>(
        in,   perZ((long)Nn*128), 128,
        Wblk, Z(),                128,
        nullptr, Z(),
        Wh, perZ((long)Nn*128), 128, 128);
    s1s2_k<<<(Zc*Nn)/8, 256>>>(Wh, ablk, s1, s2, Zc*Nn);
    softmax_k<<<dim3(Nn, Zc), 128>>>(s1, s2, mb, att);
    // dst = lrelu( att @ Wh )
    gemm_k<1><<<dim3(2, 8, Zc), 256>>>(
        att, perZ((long)Nn*Nn), Nn,
        Wh,  perZ((long)Nn*128), 128,
        nullptr, Z(),
        dst, perZ((long)Nn*128), 128, Nn);
}

extern "C" void kernel_launch(void* const* d_in, const int* in_sizes, int n_in,
                              void* d_out, int out_size)
{
    const float* x      = (const float*)d_in[0];
    const int*   adj    = (const int*)  d_in[1];
    // d_in[2] = layer_id (unused by reference)
    const float* f1w1 = (const float*)d_in[3];  const float* f1b1 = (const float*)d_in[4];
    const float* f1w2 = (const float*)d_in[5];  const float* f1b2 = (const float*)d_in[6];
    const float* f2w1 = (const float*)d_in[7];  const float* f2b1 = (const float*)d_in[8];
    const float* f2w2 = (const float*)d_in[9];  const float* f2b2 = (const float*)d_in[10];
    const float* f3w1 = (const float*)d_in[11]; const float* f3b1 = (const float*)d_in[12];
    const float* f3w2 = (const float*)d_in[13]; const float* f3b2 = (const float*)d_in[14];
    const float* att_W  = (const float*)d_in[15];
    const float* att_a  = (const float*)d_in[16];
    const float* resh_W = (const float*)d_in[17];
    const float* resh_b = (const float*)d_in[18];
    const float* out_W  = (const float*)d_in[19];
    const float* out_a  = (const float*)d_in[20];
    const float* proj_W = (const float*)d_in[21];
    const float* proj_b = (const float*)d_in[22];
    float* out = (float*)d_out;

    float *bufA, *bufB, *tmp, *hp2, *Wh, *att, *s1, *s2, *hf, *ht;
    unsigned *mask, *maskT;
    cudaGetSymbolAddress((void**)&bufA, g_bufA);
    cudaGetSymbolAddress((void**)&bufB, g_bufB);
    cudaGetSymbolAddress((void**)&tmp,  g_tmp);
    cudaGetSymbolAddress((void**)&hp2,  g_hp2);
    cudaGetSymbolAddress((void**)&Wh,   g_Wh);
    cudaGetSymbolAddress((void**)&att,  g_att);
    cudaGetSymbolAddress((void**)&s1,   g_s1);
    cudaGetSymbolAddress((void**)&s2,   g_s2);
    cudaGetSymbolAddress((void**)&hf,   g_hf);
    cudaGetSymbolAddress((void**)&ht,   g_ht);
    cudaGetSymbolAddress((void**)&mask,  g_mask);
    cudaGetSymbolAddress((void**)&maskT, g_maskT);

    // masks
    maskbuild_k<<<dim3(Nn, Bq), 512>>>(adj, mask, maskT);

    // ---- FEL ----
    gemm_k<1><<<dim3(2, 64, 1), 256>>>(x, Z(), 32,  f1w1, Z(), 128, f1b1, Z(), bufB, Z(), 128, 32);
    gemm_k<1><<<dim3(2, 64, 1), 256>>>(bufB, Z(), 128, f1w2, Z(), 128, f1b2, Z(), bufA, Z(), 128, 128);   // = res
    gemm_k<1><<<dim3(4, 64, 1), 256>>>(bufA, Z(), 128, f2w1, Z(), 256, f2b1, Z(), tmp,  Z(), 256, 128);
    gemm_k<1><<<dim3(2, 64, 1), 256>>>(tmp,  Z(), 256, f2w2, Z(), 128, f2b2, Z(), bufB, Z(), 128, 256);
    ln_res_k<<<MROWS, 128>>>(bufB, bufA, bufA);                                                            // x = LN(h+res)
    gemm_k<1><<<dim3(4, 64, 1), 256>>>(bufA, Z(), 128, f3w1, Z(), 256, f3b1, Z(), tmp,  Z(), 256, 128);
    gemm_k<0><<<dim3(2, 64, 1), 256>>>(tmp,  Z(), 256, f3w2, Z(), 128, f3b2, Z(), bufB, Z(), 128, 256);
    ln_res_k<<<MROWS, 128>>>(bufB, bufA, bufA);                                                            // h = LN(h+res)

    // ---- forward chain (mask) ----
    for (int i = 0; i < 3; i++)
        attn_block(bufA, bufA, i, mask, att_W, att_a, resh_W, resh_b, Wh, att, hp2, tmp, s1, s2);
    out_gat(bufA, hf, 0, mask, out_W, out_a, Wh, att, s1, s2);

    // ---- transposed chain (mask_t), seeded from hf ----
    attn_block(hf,   bufB, 3, maskT, att_W, att_a, resh_W, resh_b, Wh, att, hp2, tmp, s1, s2);
    attn_block(bufB, bufB, 4, maskT, att_W, att_a, resh_W, resh_b, Wh, att, hp2, tmp, s1, s2);
    attn_block(bufB, bufB, 5, maskT, att_W, att_a, resh_W, resh_b, Wh, att, hp2, tmp, s1, s2);
    out_gat(bufB, ht, 1, maskT, out_W, out_a, Wh, att, s1, s2);

    // ---- readout ----
    final_k<<<Bq, 256>>>(hf, ht, proj_W, proj_b, out);
    (void)in_sizes; (void)n_in; (void)out_size;
}